// round 7
// baseline (speedup 1.0000x reference)
#include <cuda_runtime.h>
#include <cstdint>

#define N_NODES 40000
#define N_EDGES 400000
#define H2f 0.01f
#define LN_EPS 1e-5f

// ---------------- device scratch (allocation-free rule: __device__ globals) ----
__device__ float g_xn[N_NODES * 64];
__device__ float g_xn_old[N_NODES * 64];
__device__ float g_tmp_n[N_NODES * 64];
__device__ float g_si[N_NODES * 64];
__device__ float g_sj[N_NODES * 64];
__device__ float g_xe[N_EDGES * 64];
__device__ float g_xe_old[N_EDGES * 64];
__device__ float g_tmp_e[N_EDGES * 64];
__device__ double g_stats[16];   // zero-initialized; finalize re-zeroes after use
__device__ float g_mr[16];       // (mean, rstd) pairs

// Static device-side pointer table: resolved at module load, no host API needed.
#define B_XN 0
#define B_XN_OLD 1
#define B_TMP_N 2
#define B_SI 3
#define B_SJ 4
#define B_XE 5
#define B_XE_OLD 6
#define B_TMP_E 7
__device__ float* const g_tab[8] = {g_xn, g_xn_old, g_tmp_n, g_si,
                                    g_sj, g_xe, g_xe_old, g_tmp_e};

typedef unsigned long long u64;

// ---------------- packed f32x2 helpers -----------------------------------------
__device__ __forceinline__ u64 pack2(float f) {
    u64 r;
    asm("mov.b64 %0, {%1, %1};" : "=l"(r) : "f"(f));
    return r;
}
__device__ __forceinline__ void fma2(u64& d, u64 a, u64 b) {
    asm("fma.rn.f32x2 %0, %1, %2, %0;" : "+l"(d) : "l"(a), "l"(b));
}
__device__ __forceinline__ float2 unpack2(u64 v) {
    float2 r;
    asm("mov.b64 {%0, %1}, %2;" : "=f"(r.x), "=f"(r.y) : "l"(v));
    return r;
}
__device__ __forceinline__ float f4get(const float4& v, int k) {
    return k == 0 ? v.x : (k == 1 ? v.y : (k == 2 ? v.z : v.w));
}

// Inner: one input channel, 1 position, 32 outputs (16 packed pairs).
// row = 8 x ulonglong2; 8 LDS.128 feed 16 FFMA2.
__device__ __forceinline__ void doSingle(u64* acc, const ulonglong2* row, u64 f) {
#pragma unroll
    for (int q = 0; q < 8; q++) {
        ulonglong2 kk = row[q];
        fma2(acc[2 * q + 0], f, kk.x);
        fma2(acc[2 * q + 1], f, kk.y);
    }
}

// Store 32 outputs (16 packed pairs) for one position + accumulate stats.
__device__ __forceinline__ void storeAcc(float* dst, const u64* acc, float& lsum,
                                         float& lsq) {
    float4* d4 = reinterpret_cast<float4*>(dst);
#pragma unroll
    for (int q = 0; q < 8; q++) {
        float2 v0 = unpack2(acc[2 * q]), v1 = unpack2(acc[2 * q + 1]);
        float4 w = make_float4(v0.x, v0.y, v1.x, v1.y);
        d4[q] = w;
        lsum += w.x + w.y + w.z + w.w;
        lsq += w.x * w.x + w.y * w.y + w.z * w.z + w.w * w.w;
    }
}

// ---------------- block-level stat reduction -> double atomics ------------------
// scr: >=32 floats of DYNAMIC shared scratch (reused weight buffer; synced).
__device__ __forceinline__ void block_stats(float s, float q, int slot, float* scr) {
#pragma unroll
    for (int o = 16; o > 0; o >>= 1) {
        s += __shfl_down_sync(0xFFFFFFFFu, s, o);
        q += __shfl_down_sync(0xFFFFFFFFu, q, o);
    }
    int wid = threadIdx.x >> 5, lid = threadIdx.x & 31;
    int nw = (blockDim.x + 31) >> 5;
    __syncthreads();  // weights no longer needed; safe to reuse buffer
    if (lid == 0) { scr[wid] = s; scr[16 + wid] = q; }
    __syncthreads();
    if (threadIdx.x == 0) {
        float S = 0.f, Q = 0.f;
        for (int w = 0; w < nw; w++) { S += scr[w]; Q += scr[16 + w]; }
        atomicAdd(&g_stats[slot * 2 + 0], (double)S);
        atomicAdd(&g_stats[slot * 2 + 1], (double)Q);
    }
}

// ---------------- kernels -------------------------------------------------------

__global__ void k_zero2(unsigned int n4) {  // zero si and sj together
    unsigned int t = blockIdx.x * blockDim.x + threadIdx.x;
    float4 z = make_float4(0.f, 0.f, 0.f, 0.f);
    if (t < n4) {
        reinterpret_cast<float4*>(g_tab[B_SI])[t] = z;
        reinterpret_cast<float4*>(g_tab[B_SJ])[t] = z;
    }
}

// First conv: channel-major input x[CIN][P] -> out[P][64], + stats.
// Thread layout: p = blk*128 + tid>>1 (1 position), h = tid&1 (32 outputs).
// All CIN input loads hoisted up front -> MLP = CIN per thread.
template <int CIN>
__global__ void __launch_bounds__(256, 3) k_convA(const float* __restrict__ x,
                                                  const float* __restrict__ K, int outid,
                                                  int P, int slot) {
    extern __shared__ float sKs[];  // [CIN][64] transposed
    float* __restrict__ out = g_tab[outid];
    for (int t = threadIdx.x; t < CIN * 64; t += blockDim.x) {
        int c = t >> 6, o = t & 63;
        sKs[t] = K[o * CIN + c];
    }
    __syncthreads();
    int p = blockIdx.x * (blockDim.x >> 1) + (threadIdx.x >> 1);
    int h = threadIdx.x & 1;
    float lsum = 0.f, lsq = 0.f;
    if (p < P) {
        float xv[CIN];
#pragma unroll
        for (int c = 0; c < CIN; c++) xv[c] = x[(size_t)c * P + p];  // front batch
        u64 acc[16];
#pragma unroll
        for (int q = 0; q < 16; q++) acc[q] = 0ull;
        const ulonglong2* Kp = reinterpret_cast<const ulonglong2*>(sKs);
#pragma unroll
        for (int c = 0; c < CIN; c++)
            doSingle(acc, Kp + c * 16 + h * 8, pack2(xv[c]));
        storeAcc(out + (size_t)p * 64 + h * 32, acc, lsum, lsq);
    }
    block_stats(lsum, lsq, slot, sKs);
}

// Second conv: LN+ReLU on in[P][64], then K[64][64] -> out[P][64].
template <bool STATS>
__global__ void __launch_bounds__(256, 3) k_convB(int inid, const float* __restrict__ K,
                                                  int outid, int out2id, int P,
                                                  int mrslot, int statslot) {
    extern __shared__ float sKs[];  // [64][64] transposed
    const float* __restrict__ in = g_tab[inid];
    float* __restrict__ out = g_tab[outid];
    float* __restrict__ out2 = out2id >= 0 ? g_tab[out2id] : nullptr;
    for (int t = threadIdx.x; t < 64 * 64; t += blockDim.x) {
        int c = t >> 6, o = t & 63;
        sKs[t] = K[o * 64 + c];
    }
    __syncthreads();
    float m = g_mr[mrslot * 2 + 0], r = g_mr[mrslot * 2 + 1];
    int p = blockIdx.x * (blockDim.x >> 1) + (threadIdx.x >> 1);
    int h = threadIdx.x & 1;
    float lsum = 0.f, lsq = 0.f;
    if (p < P) {
        const float4* i4 = reinterpret_cast<const float4*>(in + (size_t)p * 64);
        u64 acc[16];
#pragma unroll
        for (int q = 0; q < 16; q++) acc[q] = 0ull;
        const ulonglong2* Kp = reinterpret_cast<const ulonglong2*>(sKs);
#pragma unroll 4
        for (int c4 = 0; c4 < 16; c4++) {
            float4 v = i4[c4];
#pragma unroll
            for (int k = 0; k < 4; k++) {
                int c = c4 * 4 + k;
                float t0 = (f4get(v, k) - m) * r;
                t0 = t0 > 0.f ? t0 : 0.f;
                doSingle(acc, Kp + c * 16 + h * 8, pack2(t0));
            }
        }
        storeAcc(out + (size_t)p * 64 + h * 32, acc, lsum, lsq);
        if (out2) {
            float4* a = reinterpret_cast<float4*>(out2 + (size_t)p * 64 + h * 32);
#pragma unroll
            for (int q = 0; q < 8; q++) {
                float2 v0 = unpack2(acc[2 * q]), w0 = unpack2(acc[2 * q + 1]);
                a[q] = make_float4(v0.x, v0.y, w0.x, w0.y);
            }
        }
    }
    if (STATS) block_stats(lsum, lsq, statslot, sKs);
}

__global__ void k_finalize(int slot, double count) {
    double s = g_stats[slot * 2 + 0], q = g_stats[slot * 2 + 1];
    double m = s / count;
    double var = q / count - m * m;
    g_mr[slot * 2 + 0] = (float)m;
    g_mr[slot * 2 + 1] = rsqrtf((float)var + LN_EPS);
    g_stats[slot * 2 + 0] = 0.0;  // restore zero for next graph replay
    g_stats[slot * 2 + 1] = 0.0;
}

// Fused edge feature build (gather + [intX, xe, gradX]) + KE1 conv. 49152B dyn smem.
__global__ void __launch_bounds__(256, 3) k_edgeA(const int* __restrict__ iInd,
                                                  const int* __restrict__ jInd,
                                                  const float* __restrict__ K,  // [64][192]
                                                  int outid, int slot) {
    extern __shared__ float sKs[];  // [192][64] transposed
    const float* __restrict__ xn = g_tab[B_XN];
    const float* __restrict__ xe = g_tab[B_XE];
    float* __restrict__ out = g_tab[outid];
    for (int t = threadIdx.x; t < 192 * 64; t += blockDim.x) {
        int c = t >> 6, o = t & 63;
        sKs[t] = K[o * 192 + c];
    }
    __syncthreads();
    int e = blockIdx.x * (blockDim.x >> 1) + (threadIdx.x >> 1);
    int h = threadIdx.x & 1;
    float lsum = 0.f, lsq = 0.f;
    if (e < N_EDGES) {
        int i = iInd[e], j = jInd[e];
        const float4* xi4 = reinterpret_cast<const float4*>(xn + (size_t)i * 64);
        const float4* xj4 = reinterpret_cast<const float4*>(xn + (size_t)j * 64);
        const float4* xv4 = reinterpret_cast<const float4*>(xe + (size_t)e * 64);
        u64 acc[16];
#pragma unroll
        for (int q = 0; q < 16; q++) acc[q] = 0ull;
        const ulonglong2* Kp = reinterpret_cast<const ulonglong2*>(sKs);
#pragma unroll 2
        for (int c4 = 0; c4 < 16; c4++) {
            float4 a = xi4[c4], b = xj4[c4], v = xv4[c4];
#pragma unroll
            for (int k = 0; k < 4; k++) {
                int c = c4 * 4 + k;
                float fa = f4get(a, k), fb = f4get(b, k), fx = f4get(v, k);
                doSingle(acc, Kp + c * 16 + h * 8, pack2((fa + fb) * 0.5f));   // intX
                doSingle(acc, Kp + (64 + c) * 16 + h * 8, pack2(fx));          // xe
                doSingle(acc, Kp + (128 + c) * 16 + h * 8, pack2(fa - fb));    // gradX
            }
        }
        storeAcc(out + (size_t)e * 64 + h * 32, acc, lsum, lsq);
    }
    block_stats(lsum, lsq, slot, sKs);
}

// Fused node feature build ([aveE, divE, xn]) + KN1 conv. Out + stats.
__global__ void __launch_bounds__(256, 3) k_nodeA(const float* __restrict__ K,  // [64][192]
                                                  int outid, int slot) {
    extern __shared__ float sKs[];
    const float* __restrict__ si = g_tab[B_SI];
    const float* __restrict__ sj = g_tab[B_SJ];
    const float* __restrict__ xn = g_tab[B_XN];
    float* __restrict__ out = g_tab[outid];
    for (int t = threadIdx.x; t < 192 * 64; t += blockDim.x) {
        int c = t >> 6, o = t & 63;
        sKs[t] = K[o * 192 + c];
    }
    __syncthreads();
    int p = blockIdx.x * (blockDim.x >> 1) + (threadIdx.x >> 1);
    int h = threadIdx.x & 1;
    float lsum = 0.f, lsq = 0.f;
    if (p < N_NODES) {
        const float4* a4 = reinterpret_cast<const float4*>(si + (size_t)p * 64);
        const float4* b4 = reinterpret_cast<const float4*>(sj + (size_t)p * 64);
        const float4* x4 = reinterpret_cast<const float4*>(xn + (size_t)p * 64);
        u64 acc[16];
#pragma unroll
        for (int q = 0; q < 16; q++) acc[q] = 0ull;
        const ulonglong2* Kp = reinterpret_cast<const ulonglong2*>(sKs);
#pragma unroll 2
        for (int c4 = 0; c4 < 16; c4++) {
            float4 a = a4[c4], b = b4[c4], v = x4[c4];
#pragma unroll
            for (int k = 0; k < 4; k++) {
                int c = c4 * 4 + k;
                float fa = f4get(a, k), fb = f4get(b, k), fx = f4get(v, k);
                doSingle(acc, Kp + c * 16 + h * 8, pack2((fa + fb) * 0.5f));   // aveE
                doSingle(acc, Kp + (64 + c) * 16 + h * 8, pack2(fa - fb));     // divE
                doSingle(acc, Kp + (128 + c) * 16 + h * 8, pack2(fx));         // xn
            }
        }
        storeAcc(out + (size_t)p * 64 + h * 32, acc, lsum, lsq);
    }
    block_stats(lsum, lsq, slot, sKs);
}

// Scatter xe rows into per-node sums at i (si) and j (sj) via vector red.
__global__ void k_scatter(const int* __restrict__ iInd, const int* __restrict__ jInd) {
    const float* __restrict__ xe = g_tab[B_XE];
    float* __restrict__ si = g_tab[B_SI];
    float* __restrict__ sj = g_tab[B_SJ];
    unsigned int t = blockIdx.x * blockDim.x + threadIdx.x;
    if (t >= (unsigned int)N_EDGES * 16u) return;
    int e = t >> 4, q = t & 15;
    float4 v = reinterpret_cast<const float4*>(xe)[(size_t)e * 16 + q];
    int i = __ldg(&iInd[e]), j = __ldg(&jInd[e]);
    float* pi = si + (size_t)i * 64 + q * 4;
    float* pj = sj + (size_t)j * 64 + q * 4;
    asm volatile("red.global.add.v4.f32 [%0], {%1,%2,%3,%4};" ::"l"(pi), "f"(v.x),
                 "f"(v.y), "f"(v.z), "f"(v.w)
                 : "memory");
    asm volatile("red.global.add.v4.f32 [%0], {%1,%2,%3,%4};" ::"l"(pj), "f"(v.x),
                 "f"(v.y), "f"(v.z), "f"(v.w)
                 : "memory");
}

// xe = 2*xe - xe_old + H2 * LN(dxe)
__global__ void k_update_edge(int mrslot) {
    float* __restrict__ xe = g_tab[B_XE];
    const float* __restrict__ xe_old = g_tab[B_XE_OLD];
    const float* __restrict__ dxe = g_tab[B_TMP_E];
    unsigned int t = blockIdx.x * blockDim.x + threadIdx.x;
    if (t >= (unsigned int)N_EDGES * 16u) return;
    float m = g_mr[mrslot * 2 + 0], r = g_mr[mrslot * 2 + 1];
    float4 x = reinterpret_cast<float4*>(xe)[t];
    float4 o = reinterpret_cast<const float4*>(xe_old)[t];
    float4 d = reinterpret_cast<const float4*>(dxe)[t];
    float4 w;
    w.x = 2.f * x.x - o.x + H2f * ((d.x - m) * r);
    w.y = 2.f * x.y - o.y + H2f * ((d.y - m) * r);
    w.z = 2.f * x.z - o.z + H2f * ((d.z - m) * r);
    w.w = 2.f * x.w - o.w + H2f * ((d.w - m) * r);
    reinterpret_cast<float4*>(xe)[t] = w;
}

// xn = 2*xn - xn_old + H2 * dxn
__global__ void k_update_node() {
    float* __restrict__ xn = g_tab[B_XN];
    const float* __restrict__ xn_old = g_tab[B_XN_OLD];
    const float* __restrict__ dxn = g_tab[B_TMP_N];
    unsigned int t = blockIdx.x * blockDim.x + threadIdx.x;
    if (t >= (unsigned int)N_NODES * 16u) return;
    float4 x = reinterpret_cast<float4*>(xn)[t];
    float4 o = reinterpret_cast<const float4*>(xn_old)[t];
    float4 d = reinterpret_cast<const float4*>(dxn)[t];
    float4 w;
    w.x = 2.f * x.x - o.x + H2f * d.x;
    w.y = 2.f * x.y - o.y + H2f * d.y;
    w.z = 2.f * x.z - o.z + H2f * d.z;
    w.w = 2.f * x.w - o.w + H2f * d.w;
    reinterpret_cast<float4*>(xn)[t] = w;
}

// Final close conv: out[o][p] = sum_c KNclose[o][c] * xn[p][c]  (channel-major output)
__global__ void k_close(const float* __restrict__ K, float* __restrict__ out) {
    __shared__ float sKs[64 * 32];  // [c][32] transposed
    const float* __restrict__ xn = g_tab[B_XN];
    for (int t = threadIdx.x; t < 64 * 32; t += blockDim.x) {
        int c = t >> 5, o = t & 31;
        sKs[t] = K[o * 64 + c];
    }
    __syncthreads();
    int p = blockIdx.x * blockDim.x + threadIdx.x;
    if (p >= N_NODES) return;
    const float4* x4 = reinterpret_cast<const float4*>(xn + (size_t)p * 64);
    u64 acc[16];
#pragma unroll
    for (int q = 0; q < 16; q++) acc[q] = 0ull;
#pragma unroll 2
    for (int c4 = 0; c4 < 16; c4++) {
        float4 v = x4[c4];
#pragma unroll
        for (int k = 0; k < 4; k++) {
            int c = c4 * 4 + k;
            u64 f2 = pack2(f4get(v, k));
            const ulonglong2* row = reinterpret_cast<const ulonglong2*>(sKs + c * 32);
#pragma unroll
            for (int q = 0; q < 8; q++) {
                ulonglong2 kk = row[q];
                fma2(acc[2 * q + 0], f2, kk.x);
                fma2(acc[2 * q + 1], f2, kk.y);
            }
        }
    }
#pragma unroll
    for (int q = 0; q < 8; q++) {
        float2 v0 = unpack2(acc[2 * q]), v1 = unpack2(acc[2 * q + 1]);
        out[(size_t)(4 * q + 0) * N_NODES + p] = v0.x;
        out[(size_t)(4 * q + 1) * N_NODES + p] = v0.y;
        out[(size_t)(4 * q + 2) * N_NODES + p] = v1.x;
        out[(size_t)(4 * q + 3) * N_NODES + p] = v1.y;
    }
}

// Transpose xe [E][64] -> out [64][E] (tiled)
__global__ void k_xe_out(float* __restrict__ out) {
    __shared__ float tile[32][33];
    const float* __restrict__ xe = g_tab[B_XE];
    int e0 = blockIdx.x * 32;
    int c0 = blockIdx.y * 32;
    int tx = threadIdx.x, ty = threadIdx.y;
    tile[ty][tx] = xe[(size_t)(e0 + ty) * 64 + c0 + tx];
    __syncthreads();
    out[(size_t)(c0 + ty) * N_EDGES + e0 + tx] = tile[tx][ty];
}

// ---------------- launch --------------------------------------------------------
extern "C" void kernel_launch(void* const* d_in, const int* in_sizes, int n_in,
                              void* d_out, int out_size) {
    const float* xn_in = (const float*)d_in[0];
    const float* xe_in = (const float*)d_in[1];
    const int* iInd = (const int*)d_in[2];
    const int* jInd = (const int*)d_in[3];
    const float* K1N = (const float*)d_in[4];
    const float* K2N = (const float*)d_in[5];
    const float* K1E = (const float*)d_in[6];
    const float* K2E = (const float*)d_in[7];
    const float* KNc = (const float*)d_in[8];
    const float* KE1 = (const float*)d_in[9];
    const float* KE2 = (const float*)d_in[10];
    const float* KN1 = (const float*)d_in[11];
    const float* KN2 = (const float*)d_in[12];
    float* out = (float*)d_out;

    const int T = 256;
    // 1 position per thread-pair-half => 128 positions per block of 256 threads
    const int gN = (N_NODES + 127) / 128;
    const int gE = (N_EDGES + 127) / 128;
    const size_t sh16 = 16 * 64 * sizeof(float);
    const size_t sh64 = 64 * 64 * sizeof(float);
    const size_t sh192 = 192 * 64 * sizeof(float);  // 49152 B == default cap, 0 static
    const double CNT_N = 64.0 * N_NODES, CNT_E = 64.0 * N_EDGES;
    const unsigned int n4N = (unsigned int)N_NODES * 16u;

    // ---- open nodes: conv -> global LN -> relu -> conv ; anchor copy to xn_old
    k_convA<16><<<gN, T, sh16>>>(xn_in, K1N, B_TMP_N, N_NODES, 0);
    k_finalize<<<1, 1>>>(0, CNT_N);
    k_convB<false><<<gN, T, sh64>>>(B_TMP_N, K2N, B_XN, B_XN_OLD, N_NODES, 0, 0);

    // ---- open edges
    k_convA<16><<<gE, T, sh16>>>(xe_in, K1E, B_TMP_E, N_EDGES, 1);
    k_finalize<<<1, 1>>>(1, CNT_E);
    k_convB<false><<<gE, T, sh64>>>(B_TMP_E, K2E, B_XE, B_XE_OLD, N_EDGES, 1, 1);

    for (int l = 0; l < 2; l++) {
        // node-side scatter sums from current xe (before updates)
        k_zero2<<<(n4N + T - 1) / T, T>>>(n4N);
        k_scatter<<<(N_EDGES * 16) / T, T>>>(iInd, jInd);

        // edge path: gather+concat+KE1 -> LN stats -> LN+relu+KE2 (+stats for outer LN)
        k_edgeA<<<gE, T, sh192>>>(iInd, jInd, KE1 + (size_t)l * 64 * 192, B_TMP_E, 2);
        k_finalize<<<1, 1>>>(2, CNT_E);
        k_convB<true><<<gE, T, sh64>>>(B_TMP_E, KE2 + (size_t)l * 64 * 64, B_TMP_E, -1,
                                       N_EDGES, 2, 3);
        k_finalize<<<1, 1>>>(3, CNT_E);

        // node path: [aveE, divE, xn]+KN1 -> LN stats -> LN+relu+KN2 (no outer LN)
        k_nodeA<<<gN, T, sh192>>>(KN1 + (size_t)l * 64 * 192, B_TMP_N, 4);
        k_finalize<<<1, 1>>>(4, CNT_N);
        k_convB<false><<<gN, T, sh64>>>(B_TMP_N, KN2 + (size_t)l * 64 * 64, B_TMP_N, -1,
                                        N_NODES, 4, 0);

        // leapfrog updates (after both paths consumed pre-update xn/xe)
        k_update_node<<<(N_NODES * 16 + T - 1) / T, T>>>();
        k_update_edge<<<(N_EDGES * 16) / T, T>>>(3);
    }

    // outputs: xn -> KNclose (channel-major), then xe transposed to channel-major
    k_close<<<(N_NODES + T - 1) / T, T>>>(KNc, out);
    dim3 tb(32, 32), tg(N_EDGES / 32, 2);
    k_xe_out<<<tg, tb>>>(out + (size_t)32 * N_NODES);
}

// round 8
// speedup vs baseline: 1.8657x; 1.8657x over previous
#include <cuda_runtime.h>
#include <cstdint>

#define N_NODES 40000
#define N_EDGES 400000
#define H2f 0.01f
#define LN_EPS 1e-5f
#define MTILE 256
#define KC 16

// ---------------- device scratch (allocation-free rule: __device__ globals) ----
__device__ float g_xn[N_NODES * 64];
__device__ float g_xn_old[N_NODES * 64];
__device__ float g_tmp_n[N_NODES * 64];
__device__ float g_si[N_NODES * 64];
__device__ float g_sj[N_NODES * 64];
__device__ float g_xe[N_EDGES * 64];
__device__ float g_xe_old[N_EDGES * 64];
__device__ float g_tmp_e[N_EDGES * 64];
__device__ double g_stats[16];   // zero-initialized; finalize re-zeroes after use
__device__ float g_mr[16];       // (mean, rstd) pairs

typedef unsigned long long u64;
__device__ u64 g_wpack[37888];   // all packed weights: [k][32 output-pairs] per matrix

// Packed-weight offsets (u64 units). Order: K1N,K2N,K1E,K2E,KE1(x2),KE2(x2),KN1(x2),KN2(x2)
#define OFF_K1N 0
#define OFF_K2N 512
#define OFF_K1E 2560
#define OFF_K2E 3072
#define OFF_KE1 5120    /* stride 6144 per layer */
#define OFF_KE2 17408   /* stride 2048 */
#define OFF_KN1 21504   /* stride 6144 */
#define OFF_KN2 33792   /* stride 2048 */

// Static device-side pointer table: resolved at module load, no host API needed.
#define B_XN 0
#define B_XN_OLD 1
#define B_TMP_N 2
#define B_SI 3
#define B_SJ 4
#define B_XE 5
#define B_XE_OLD 6
#define B_TMP_E 7
__device__ float* const g_tab[8] = {g_xn, g_xn_old, g_tmp_n, g_si,
                                    g_sj, g_xe, g_xe_old, g_tmp_e};

// ---------------- packed f32x2 helpers -----------------------------------------
__device__ __forceinline__ u64 pack2(float f) {
    u64 r;
    asm("mov.b64 %0, {%1, %1};" : "=l"(r) : "f"(f));
    return r;
}
__device__ __forceinline__ void fma2(u64& d, u64 a, u64 b) {
    asm("fma.rn.f32x2 %0, %1, %2, %0;" : "+l"(d) : "l"(a), "l"(b));
}
__device__ __forceinline__ float2 unpack2(u64 v) {
    float2 r;
    asm("mov.b64 {%0, %1}, %2;" : "=f"(r.x), "=f"(r.y) : "l"(v));
    return r;
}
__device__ __forceinline__ float4 ave4(float4 a, float4 b) {
    return make_float4((a.x + b.x) * 0.5f, (a.y + b.y) * 0.5f, (a.z + b.z) * 0.5f,
                       (a.w + b.w) * 0.5f);
}
__device__ __forceinline__ float4 sub4(float4 a, float4 b) {
    return make_float4(a.x - b.x, a.y - b.y, a.z - b.z, a.w - b.w);
}

// ---------------- block-level stat reduction -> double atomics ------------------
__device__ __forceinline__ void block_stats(float s, float q, int slot, float* scr) {
#pragma unroll
    for (int o = 16; o > 0; o >>= 1) {
        s += __shfl_down_sync(0xFFFFFFFFu, s, o);
        q += __shfl_down_sync(0xFFFFFFFFu, q, o);
    }
    int wid = threadIdx.x >> 5, lid = threadIdx.x & 31;
    int nw = (blockDim.x + 31) >> 5;
    __syncthreads();  // smem no longer needed for tiles; safe to reuse
    if (lid == 0) { scr[wid] = s; scr[16 + wid] = q; }
    __syncthreads();
    if (threadIdx.x == 0) {
        float S = 0.f, Q = 0.f;
        for (int w = 0; w < nw; w++) { S += scr[w]; Q += scr[16 + w]; }
        atomicAdd(&g_stats[slot * 2 + 0], (double)S);
        atomicAdd(&g_stats[slot * 2 + 1], (double)Q);
    }
}

// ---------------- weight packing ------------------------------------------------
// Each source W is [64][K] out-major. Packed: wp[k*32 + o] = (W[2o][k], W[2o+1][k]).
__global__ void k_packall(const float* __restrict__ K1N, const float* __restrict__ K2N,
                          const float* __restrict__ K1E, const float* __restrict__ K2E,
                          const float* __restrict__ KE1, const float* __restrict__ KE2,
                          const float* __restrict__ KN1, const float* __restrict__ KN2) {
    int t = blockIdx.x * blockDim.x + threadIdx.x;
    if (t >= 37888) return;
    const int Ks[12] = {16, 64, 16, 64, 192, 192, 64, 64, 192, 192, 64, 64};
    const int offs[12] = {OFF_K1N, OFF_K2N, OFF_K1E, OFF_K2E,
                          OFF_KE1, OFF_KE1 + 6144, OFF_KE2, OFF_KE2 + 2048,
                          OFF_KN1, OFF_KN1 + 6144, OFF_KN2, OFF_KN2 + 2048};
    const float* Ws[12] = {K1N, K2N, K1E, K2E, KE1, KE1 + 192 * 64, KE2, KE2 + 64 * 64,
                           KN1, KN1 + 192 * 64, KN2, KN2 + 64 * 64};
    int s = 0;
#pragma unroll
    for (int q = 1; q < 12; q++)
        if (t >= offs[q]) s = q;
    int loc = t - offs[s];
    int K = Ks[s];
    int k = loc >> 5, o = loc & 31;
    const float* W = Ws[s];
    float w0 = W[(2 * o) * K + k];
    float w1 = W[(2 * o + 1) * K + k];
    u64 r;
    asm("mov.b64 %0, {%1, %2};" : "=l"(r) : "f"(w0), "f"(w1));
    g_wpack[t] = r;
}

// ---------------- unified tiled GEMM ------------------------------------------
// out[P][64] = A[P][K] @ W[K][64].
// MODE 0: A = xraw channel-major [K][P]                  (opening convs)
// MODE 1: A = relu((in[P][64]-m)*r)                      (second convs, K=64)
// MODE 2: A = [ (xn_i+xn_j)/2 | xe | xn_i-xn_j ]         (edge features, K=192)
// MODE 3: A = [ (si+sj)/2 | si-sj | xn ]                 (node features, K=192)
// Thread tile: 8 positions x 8 outputs. Block tile: 256 positions x 64 outputs.
template <int MODE>
__global__ void __launch_bounds__(256) k_gemm(const float* __restrict__ xraw,
                                              const int* __restrict__ iInd,
                                              const int* __restrict__ jInd, int inid,
                                              int outid, int out2id, int woff, int P,
                                              int K, int slot, int mrslot) {
    __shared__ float As[KC][MTILE];  // 16KB: transposed feature chunk
    __shared__ u64 Bs[KC][32];       // 4KB: packed weight chunk
    int tid = threadIdx.x;
    int p0 = blockIdx.x * MTILE;
    int gp = p0 + tid;  // staging position owned by this thread
    bool valid = gp < P;
    int gps = valid ? gp : 0;

    const float4 *r0 = nullptr, *r1 = nullptr, *r2 = nullptr;
    float lm = 0.f, lr = 0.f;
    if (MODE == 1) {
        lm = g_mr[mrslot * 2 + 0];
        lr = g_mr[mrslot * 2 + 1];
        r0 = reinterpret_cast<const float4*>(g_tab[inid] + (size_t)gps * 64);
    } else if (MODE == 2) {
        int i = valid ? iInd[gp] : 0;
        int j = valid ? jInd[gp] : 0;
        r0 = reinterpret_cast<const float4*>(g_xn + (size_t)i * 64);
        r1 = reinterpret_cast<const float4*>(g_xn + (size_t)j * 64);
        r2 = reinterpret_cast<const float4*>(g_xe + (size_t)gps * 64);
    } else if (MODE == 3) {
        r0 = reinterpret_cast<const float4*>(g_si + (size_t)gps * 64);
        r1 = reinterpret_cast<const float4*>(g_sj + (size_t)gps * 64);
        r2 = reinterpret_cast<const float4*>(g_xn + (size_t)gps * 64);
    }

    int tx = tid & 7;   // output octet: outputs [tx*8, tx*8+8)
    int ty = tid >> 3;  // position octet: positions [p0+ty*8, p0+ty*8+8)
    u64 acc[8][4];
#pragma unroll
    for (int mm = 0; mm < 8; mm++)
#pragma unroll
        for (int q = 0; q < 4; q++) acc[mm][q] = 0ull;

    const u64* Wp = g_wpack + woff;
    int nchunk = K >> 4;
    for (int cb = 0; cb < nchunk; cb++) {
        int c0 = cb * KC;
        // ---- stage B chunk (coalesced ulonglong2 copies)
        {
            int k = tid >> 4, o2 = (tid & 15) << 1;
            ulonglong2 w =
                *reinterpret_cast<const ulonglong2*>(Wp + (size_t)(c0 + k) * 32 + o2);
            *reinterpret_cast<ulonglong2*>(&Bs[k][o2]) = w;
        }
        // ---- stage A chunk (transposed; thread owns one position column)
        if (MODE == 0) {
#pragma unroll
            for (int k = 0; k < KC; k++)
                As[k][tid] = valid ? xraw[(size_t)(c0 + k) * P + gp] : 0.f;
        } else if (MODE == 1) {
#pragma unroll
            for (int q = 0; q < 4; q++) {
                float4 v = r0[(c0 >> 2) + q];
                float t0 = (v.x - lm) * lr, t1 = (v.y - lm) * lr;
                float t2 = (v.z - lm) * lr, t3 = (v.w - lm) * lr;
                t0 = t0 > 0.f ? t0 : 0.f;
                t1 = t1 > 0.f ? t1 : 0.f;
                t2 = t2 > 0.f ? t2 : 0.f;
                t3 = t3 > 0.f ? t3 : 0.f;
                if (!valid) { t0 = t1 = t2 = t3 = 0.f; }
                As[q * 4 + 0][tid] = t0;
                As[q * 4 + 1][tid] = t1;
                As[q * 4 + 2][tid] = t2;
                As[q * 4 + 3][tid] = t3;
            }
        } else {
#pragma unroll
            for (int q = 0; q < 4; q++) {
                float4 w;
                if (c0 < 64) {  // segment 0: average (both modes)
                    w = ave4(r0[(c0 >> 2) + q], r1[(c0 >> 2) + q]);
                } else if (c0 < 128) {  // segment 1: xe (edge) / si-sj (node)
                    int qq = ((c0 - 64) >> 2) + q;
                    w = (MODE == 2) ? r2[qq] : sub4(r0[qq], r1[qq]);
                } else {  // segment 2: grad (edge) / xn (node)
                    int qq = ((c0 - 128) >> 2) + q;
                    w = (MODE == 2) ? sub4(r0[qq], r1[qq]) : r2[qq];
                }
                if (!valid) w = make_float4(0.f, 0.f, 0.f, 0.f);
                As[q * 4 + 0][tid] = w.x;
                As[q * 4 + 1][tid] = w.y;
                As[q * 4 + 2][tid] = w.z;
                As[q * 4 + 3][tid] = w.w;
            }
        }
        __syncthreads();
        // ---- register-tiled FMA: 4 LDS.128 feed 32 FFMA2 per k
#pragma unroll
        for (int k = 0; k < KC; k++) {
            float4 a0 = *reinterpret_cast<const float4*>(&As[k][ty * 8]);
            float4 a1 = *reinterpret_cast<const float4*>(&As[k][ty * 8 + 4]);
            ulonglong2 b0 = *reinterpret_cast<const ulonglong2*>(&Bs[k][tx * 4]);
            ulonglong2 b1 = *reinterpret_cast<const ulonglong2*>(&Bs[k][tx * 4 + 2]);
            float av[8] = {a0.x, a0.y, a0.z, a0.w, a1.x, a1.y, a1.z, a1.w};
#pragma unroll
            for (int mm = 0; mm < 8; mm++) {
                u64 am = pack2(av[mm]);
                fma2(acc[mm][0], am, b0.x);
                fma2(acc[mm][1], am, b0.y);
                fma2(acc[mm][2], am, b1.x);
                fma2(acc[mm][3], am, b1.y);
            }
        }
        __syncthreads();
    }
    // ---- epilogue: each thread stores 8 pos x 8 outputs + stats
    float* outp = g_tab[outid];
    float* out2p = out2id >= 0 ? g_tab[out2id] : nullptr;
    float lsum = 0.f, lsq = 0.f;
#pragma unroll
    for (int mm = 0; mm < 8; mm++) {
        int pp = p0 + ty * 8 + mm;
        if (pp < P) {
            float2 v0 = unpack2(acc[mm][0]), v1 = unpack2(acc[mm][1]);
            float2 v2 = unpack2(acc[mm][2]), v3 = unpack2(acc[mm][3]);
            float4 w0 = make_float4(v0.x, v0.y, v1.x, v1.y);
            float4 w1 = make_float4(v2.x, v2.y, v3.x, v3.y);
            float4* dst = reinterpret_cast<float4*>(outp + (size_t)pp * 64 + tx * 8);
            dst[0] = w0;
            dst[1] = w1;
            if (out2p) {
                float4* d2 = reinterpret_cast<float4*>(out2p + (size_t)pp * 64 + tx * 8);
                d2[0] = w0;
                d2[1] = w1;
            }
            lsum += w0.x + w0.y + w0.z + w0.w + w1.x + w1.y + w1.z + w1.w;
            lsq += w0.x * w0.x + w0.y * w0.y + w0.z * w0.z + w0.w * w0.w +
                   w1.x * w1.x + w1.y * w1.y + w1.z * w1.z + w1.w * w1.w;
        }
    }
    if (slot >= 0) block_stats(lsum, lsq, slot, &As[0][0]);
}

// ---------------- small kernels (unchanged from R6) ----------------------------
__global__ void k_zero2(unsigned int n4) {
    unsigned int t = blockIdx.x * blockDim.x + threadIdx.x;
    float4 z = make_float4(0.f, 0.f, 0.f, 0.f);
    if (t < n4) {
        reinterpret_cast<float4*>(g_tab[B_SI])[t] = z;
        reinterpret_cast<float4*>(g_tab[B_SJ])[t] = z;
    }
}

__global__ void k_finalize(int slot, double count) {
    double s = g_stats[slot * 2 + 0], q = g_stats[slot * 2 + 1];
    double m = s / count;
    double var = q / count - m * m;
    g_mr[slot * 2 + 0] = (float)m;
    g_mr[slot * 2 + 1] = rsqrtf((float)var + LN_EPS);
    g_stats[slot * 2 + 0] = 0.0;  // restore zero for next graph replay
    g_stats[slot * 2 + 1] = 0.0;
}

__global__ void k_scatter(const int* __restrict__ iInd, const int* __restrict__ jInd) {
    const float* __restrict__ xe = g_tab[B_XE];
    float* __restrict__ si = g_tab[B_SI];
    float* __restrict__ sj = g_tab[B_SJ];
    unsigned int t = blockIdx.x * blockDim.x + threadIdx.x;
    if (t >= (unsigned int)N_EDGES * 16u) return;
    int e = t >> 4, q = t & 15;
    float4 v = reinterpret_cast<const float4*>(xe)[(size_t)e * 16 + q];
    int i = __ldg(&iInd[e]), j = __ldg(&jInd[e]);
    float* pi = si + (size_t)i * 64 + q * 4;
    float* pj = sj + (size_t)j * 64 + q * 4;
    asm volatile("red.global.add.v4.f32 [%0], {%1,%2,%3,%4};" ::"l"(pi), "f"(v.x),
                 "f"(v.y), "f"(v.z), "f"(v.w)
                 : "memory");
    asm volatile("red.global.add.v4.f32 [%0], {%1,%2,%3,%4};" ::"l"(pj), "f"(v.x),
                 "f"(v.y), "f"(v.z), "f"(v.w)
                 : "memory");
}

__global__ void k_update_edge(int mrslot) {
    float* __restrict__ xe = g_tab[B_XE];
    const float* __restrict__ xe_old = g_tab[B_XE_OLD];
    const float* __restrict__ dxe = g_tab[B_TMP_E];
    unsigned int t = blockIdx.x * blockDim.x + threadIdx.x;
    if (t >= (unsigned int)N_EDGES * 16u) return;
    float m = g_mr[mrslot * 2 + 0], r = g_mr[mrslot * 2 + 1];
    float4 x = reinterpret_cast<float4*>(xe)[t];
    float4 o = reinterpret_cast<const float4*>(xe_old)[t];
    float4 d = reinterpret_cast<const float4*>(dxe)[t];
    float4 w;
    w.x = 2.f * x.x - o.x + H2f * ((d.x - m) * r);
    w.y = 2.f * x.y - o.y + H2f * ((d.y - m) * r);
    w.z = 2.f * x.z - o.z + H2f * ((d.z - m) * r);
    w.w = 2.f * x.w - o.w + H2f * ((d.w - m) * r);
    reinterpret_cast<float4*>(xe)[t] = w;
}

__global__ void k_update_node() {
    float* __restrict__ xn = g_tab[B_XN];
    const float* __restrict__ xn_old = g_tab[B_XN_OLD];
    const float* __restrict__ dxn = g_tab[B_TMP_N];
    unsigned int t = blockIdx.x * blockDim.x + threadIdx.x;
    if (t >= (unsigned int)N_NODES * 16u) return;
    float4 x = reinterpret_cast<float4*>(xn)[t];
    float4 o = reinterpret_cast<const float4*>(xn_old)[t];
    float4 d = reinterpret_cast<const float4*>(dxn)[t];
    float4 w;
    w.x = 2.f * x.x - o.x + H2f * d.x;
    w.y = 2.f * x.y - o.y + H2f * d.y;
    w.z = 2.f * x.z - o.z + H2f * d.z;
    w.w = 2.f * x.w - o.w + H2f * d.w;
    reinterpret_cast<float4*>(xn)[t] = w;
}

__global__ void k_close(const float* __restrict__ K, float* __restrict__ out) {
    __shared__ float sKs[64 * 32];  // [c][32] transposed
    const float* __restrict__ xn = g_tab[B_XN];
    for (int t = threadIdx.x; t < 64 * 32; t += blockDim.x) {
        int c = t >> 5, o = t & 31;
        sKs[t] = K[o * 64 + c];
    }
    __syncthreads();
    int p = blockIdx.x * blockDim.x + threadIdx.x;
    if (p >= N_NODES) return;
    const float4* x4 = reinterpret_cast<const float4*>(xn + (size_t)p * 64);
    u64 acc[16];
#pragma unroll
    for (int q = 0; q < 16; q++) acc[q] = 0ull;
#pragma unroll 2
    for (int c4 = 0; c4 < 16; c4++) {
        float4 v = x4[c4];
        float vv[4] = {v.x, v.y, v.z, v.w};
#pragma unroll
        for (int k = 0; k < 4; k++) {
            int c = c4 * 4 + k;
            u64 f2 = pack2(vv[k]);
            const ulonglong2* row = reinterpret_cast<const ulonglong2*>(sKs + c * 32);
#pragma unroll
            for (int q = 0; q < 8; q++) {
                ulonglong2 kk = row[q];
                fma2(acc[2 * q + 0], f2, kk.x);
                fma2(acc[2 * q + 1], f2, kk.y);
            }
        }
    }
#pragma unroll
    for (int q = 0; q < 8; q++) {
        float2 v0 = unpack2(acc[2 * q]), v1 = unpack2(acc[2 * q + 1]);
        out[(size_t)(4 * q + 0) * N_NODES + p] = v0.x;
        out[(size_t)(4 * q + 1) * N_NODES + p] = v0.y;
        out[(size_t)(4 * q + 2) * N_NODES + p] = v1.x;
        out[(size_t)(4 * q + 3) * N_NODES + p] = v1.y;
    }
}

__global__ void k_xe_out(float* __restrict__ out) {
    __shared__ float tile[32][33];
    const float* __restrict__ xe = g_tab[B_XE];
    int e0 = blockIdx.x * 32;
    int c0 = blockIdx.y * 32;
    int tx = threadIdx.x, ty = threadIdx.y;
    tile[ty][tx] = xe[(size_t)(e0 + ty) * 64 + c0 + tx];
    __syncthreads();
    out[(size_t)(c0 + ty) * N_EDGES + e0 + tx] = tile[tx][ty];
}

// ---------------- launch --------------------------------------------------------
extern "C" void kernel_launch(void* const* d_in, const int* in_sizes, int n_in,
                              void* d_out, int out_size) {
    const float* xn_in = (const float*)d_in[0];
    const float* xe_in = (const float*)d_in[1];
    const int* iInd = (const int*)d_in[2];
    const int* jInd = (const int*)d_in[3];
    const float* K1N = (const float*)d_in[4];
    const float* K2N = (const float*)d_in[5];
    const float* K1E = (const float*)d_in[6];
    const float* K2E = (const float*)d_in[7];
    const float* KNc = (const float*)d_in[8];
    const float* KE1 = (const float*)d_in[9];
    const float* KE2 = (const float*)d_in[10];
    const float* KN1 = (const float*)d_in[11];
    const float* KN2 = (const float*)d_in[12];
    float* out = (float*)d_out;

    const int T = 256;
    const int gmN = (N_NODES + MTILE - 1) / MTILE;   // 157
    const int gmE = (N_EDGES + MTILE - 1) / MTILE;   // 1563
    const double CNT_N = 64.0 * N_NODES, CNT_E = 64.0 * N_EDGES;
    const unsigned int n4N = (unsigned int)N_NODES * 16u;

    // pack ALL weights up front
    k_packall<<<(37888 + T - 1) / T, T>>>(K1N, K2N, K1E, K2E, KE1, KE2, KN1, KN2);

    // ---- open nodes: conv -> global LN -> relu -> conv ; anchor copy to xn_old
    k_gemm<0><<<gmN, T>>>(xn_in, nullptr, nullptr, -1, B_TMP_N, -1, OFF_K1N, N_NODES,
                          16, 0, -1);
    k_finalize<<<1, 1>>>(0, CNT_N);
    k_gemm<1><<<gmN, T>>>(nullptr, nullptr, nullptr, B_TMP_N, B_XN, B_XN_OLD, OFF_K2N,
                          N_NODES, 64, -1, 0);

    // ---- open edges
    k_gemm<0><<<gmE, T>>>(xe_in, nullptr, nullptr, -1, B_TMP_E, -1, OFF_K1E, N_EDGES,
                          16, 1, -1);
    k_finalize<<<1, 1>>>(1, CNT_E);
    k_gemm<1><<<gmE, T>>>(nullptr, nullptr, nullptr, B_TMP_E, B_XE, B_XE_OLD, OFF_K2E,
                          N_EDGES, 64, -1, 1);

    for (int l = 0; l < 2; l++) {
        // node-side scatter sums from current xe (before updates)
        k_zero2<<<(n4N + T - 1) / T, T>>>(n4N);
        k_scatter<<<(N_EDGES * 16) / T, T>>>(iInd, jInd);

        // edge path: gather+concat+KE1 -> LN -> relu+KE2 (+stats for outer LN)
        k_gemm<2><<<gmE, T>>>(nullptr, iInd, jInd, -1, B_TMP_E, -1,
                              OFF_KE1 + l * 6144, N_EDGES, 192, 2, -1);
        k_finalize<<<1, 1>>>(2, CNT_E);
        k_gemm<1><<<gmE, T>>>(nullptr, nullptr, nullptr, B_TMP_E, B_TMP_E, -1,
                              OFF_KE2 + l * 2048, N_EDGES, 64, 3, 2);
        k_finalize<<<1, 1>>>(3, CNT_E);

        // node path: [aveE, divE, xn]+KN1 -> LN -> relu+KN2
        k_gemm<3><<<gmN, T>>>(nullptr, nullptr, nullptr, -1, B_TMP_N, -1,
                              OFF_KN1 + l * 6144, N_NODES, 192, 4, -1);
        k_finalize<<<1, 1>>>(4, CNT_N);
        k_gemm<1><<<gmN, T>>>(nullptr, nullptr, nullptr, B_TMP_N, B_TMP_N, -1,
                              OFF_KN2 + l * 2048, N_NODES, 64, -1, 4);

        // leapfrog updates (after both paths consumed pre-update xn/xe)
        k_update_node<<<(N_NODES * 16 + T - 1) / T, T>>>();
        k_update_edge<<<(N_EDGES * 16) / T, T>>>(3);
    }

    // outputs: xn -> KNclose (channel-major), then xe transposed to channel-major
    k_close<<<(N_NODES + T - 1) / T, T>>>(KNc, out);
    dim3 tb(32, 32), tg(N_EDGES / 32, 2);
    k_xe_out<<<tg, tb>>>(out + (size_t)32 * N_NODES);
}